// round 13
// baseline (speedup 1.0000x reference)
#include <cuda_runtime.h>
#include <cstdint>

// 3x3 conv, stride 1, pad 1, single channel, X: (32, 1024, 1024) fp32.
// Persistent CTAs + double-buffered cp.async.bulk pipeline:
//   grid = 148*4 = 592 resident CTAs, each processes ~14 four-row bands
//   (strided). While band i is computed from smem buffer (i&1), the bulk
//   copy for band i+1 streams into the other buffer -> zero exposed copy
//   latency in steady state, one 24KB copy per CTA continuously in flight
//   (4 CTAs/SM = 96KB/SM outstanding), no wave tails (single launch).
// Compute: one-touch rolling 3-row register window; __stcs float4 stores.

#define IMG_W 1024
#define IMG_H 1024
#define ROWS_CTA 4
#define SM_ROWS (ROWS_CTA + 2)
#define BUF_FLOATS (SM_ROWS * IMG_W)
#define SMEM_BYTES (2 * BUF_FLOATS * 4 + 16)
#define N_CTAS (148 * 4)
#define TOTAL_BANDS (32 * 256)

__device__ __forceinline__ uint32_t smem_u32(const void* p) {
    uint32_t a;
    asm("{ .reg .u64 t; cvta.to.shared.u64 t, %1; cvt.u32.u64 %0, t; }"
        : "=r"(a) : "l"(p));
    return a;
}

__global__ __launch_bounds__(256) void conv3x3_kernel(
    const float* __restrict__ X,
    const float* __restrict__ Wt,
    float* __restrict__ Y)
{
    extern __shared__ __align__(128) float smem[];
    // Layout: [buf0 rows][buf1 rows][2 mbarriers]
    unsigned long long* mbar =
        reinterpret_cast<unsigned long long*>(&smem[2 * BUF_FLOATS]);

    const int tid  = threadIdx.x;
    const int c0   = tid << 2;            // 4 cols per thread (covers 1024)
    const size_t plane = (size_t)IMG_W * IMG_H;

    const uint32_t mbar_a0 = smem_u32(&mbar[0]);
    const uint32_t mbar_a1 = smem_u32(&mbar[1]);
    const uint32_t sm_a    = smem_u32(smem);

    if (tid == 0) {
        asm volatile("mbarrier.init.shared.b64 [%0], 1;" :: "r"(mbar_a0) : "memory");
        asm volatile("mbarrier.init.shared.b64 [%0], 1;" :: "r"(mbar_a1) : "memory");
    }
    __syncthreads();

    float w[9];
#pragma unroll
    for (int i = 0; i < 9; i++) w[i] = __ldg(Wt + i);

    // Issue the bulk copy for global band gb into buffer b (tid 0 only).
#define ISSUE_COPY(gb, b)                                                     \
    do {                                                                      \
        const int _batch = (gb) >> 8;                                         \
        const int _band  = (gb) & 255;                                        \
        const int _r0    = _band << 2;                                        \
        const int _rf    = _r0 - 1;                                           \
        const int _gs    = _rf < 0 ? 0 : _rf;                                 \
        const int _gei   = _r0 + ROWS_CTA;                                    \
        const int _ge    = _gei > (IMG_H - 1) ? (IMG_H - 1) : _gei;           \
        const uint32_t _nb  = (uint32_t)(_ge - _gs + 1) * IMG_W * 4u;         \
        const uint32_t _dst = sm_a + ((uint32_t)(b) * BUF_FLOATS              \
                              + (uint32_t)(_gs - _rf) * IMG_W) * 4u;          \
        const float*   _src = X + (size_t)_batch * plane + (size_t)_gs * IMG_W; \
        const uint32_t _mb  = (b) ? mbar_a1 : mbar_a0;                        \
        asm volatile("mbarrier.arrive.expect_tx.shared.b64 _, [%0], %1;"      \
                     :: "r"(_mb), "r"(_nb) : "memory");                       \
        asm volatile(                                                         \
            "cp.async.bulk.shared::cta.global.mbarrier::complete_tx::bytes "  \
            "[%0], [%1], %2, [%3];"                                           \
            :: "r"(_dst), "l"(_src), "r"(_nb), "r"(_mb) : "memory");          \
    } while (0)

    // Prologue: first band's copy.
    if ((int)blockIdx.x < TOTAL_BANDS && tid == 0) {
        ISSUE_COPY((int)blockIdx.x, 0);
    }

    int it = 0;
    for (int gb = blockIdx.x; gb < TOTAL_BANDS; gb += gridDim.x, ++it) {
        const int buf = it & 1;
        const int par = (it >> 1) & 1;    // parity of this buffer's use

        // Issue next band's copy into the other buffer (freed by the
        // __syncthreads at the end of the previous iteration).
        const int nxt = gb + (int)gridDim.x;
        if (nxt < TOTAL_BANDS && tid == 0) {
            ISSUE_COPY(nxt, buf ^ 1);
        }

        // Wait for this band's copy.
        const uint32_t mb = buf ? mbar_a1 : mbar_a0;
        asm volatile(
            "{\n\t"
            ".reg .pred P;\n\t"
            "WAIT_%=:\n\t"
            "mbarrier.try_wait.parity.acquire.cta.shared::cta.b64 P, [%0], %1;\n\t"
            "@!P bra WAIT_%=;\n\t"
            "}"
            :: "r"(mb), "r"(par) : "memory");

        const int batch = gb >> 8;
        const int band  = gb & 255;
        const int r0    = band << 2;
        float* bufp     = &smem[buf * BUF_FLOATS];

        // Zero pad rows (slots the copy never writes) for edge bands.
        if (r0 == 0) {
            float4 z = make_float4(0.f, 0.f, 0.f, 0.f);
            *reinterpret_cast<float4*>(&bufp[c0]) = z;
        }
        if (r0 + ROWS_CTA > IMG_H - 1) {
            float4 z = make_float4(0.f, 0.f, 0.f, 0.f);
            *reinterpret_cast<float4*>(&bufp[(SM_ROWS - 1) * IMG_W + c0]) = z;
        }
        __syncthreads();   // pad zeros visible to neighbor threads

        float* Yb = Y + (size_t)batch * plane;

        // Rolling 3-row register window; buf row k = input row r0 + k - 1.
        float b3[3][6];
#define LOAD_SMROW(dstbuf, k)                                                 \
        do {                                                                  \
            const float* rp = &bufp[(k) * IMG_W];                             \
            const float4 v = *reinterpret_cast<const float4*>(rp + c0);       \
            (dstbuf)[1] = v.x; (dstbuf)[2] = v.y;                             \
            (dstbuf)[3] = v.z; (dstbuf)[4] = v.w;                             \
            (dstbuf)[0] = (c0 > 0)         ? rp[c0 - 1] : 0.0f;               \
            (dstbuf)[5] = (c0 + 4 < IMG_W) ? rp[c0 + 4] : 0.0f;               \
        } while (0)

        LOAD_SMROW(b3[0], 0);
        LOAD_SMROW(b3[1], 1);

#pragma unroll
        for (int i = 0; i < ROWS_CTA; i++) {
            LOAD_SMROW(b3[(i + 2) % 3], i + 2);

            const float* t0 = b3[i % 3];
            const float* t1 = b3[(i + 1) % 3];
            const float* t2 = b3[(i + 2) % 3];

            float acc[4];
#pragma unroll
            for (int j = 0; j < 4; j++) {
                float a;
                a = fmaf(w[0], t0[j], fmaf(w[1], t0[j + 1], w[2] * t0[j + 2]));
                a = fmaf(w[3], t1[j], fmaf(w[4], t1[j + 1], fmaf(w[5], t1[j + 2], a)));
                a = fmaf(w[6], t2[j], fmaf(w[7], t2[j + 1], fmaf(w[8], t2[j + 2], a)));
                acc[j] = a;
            }
            float4 o;
            o.x = acc[0]; o.y = acc[1]; o.z = acc[2]; o.w = acc[3];
            __stcs(reinterpret_cast<float4*>(Yb + (size_t)(r0 + i) * IMG_W + c0), o);
        }
#undef LOAD_SMROW

        __syncthreads();   // all reads of this buffer done before it's refilled
    }
#undef ISSUE_COPY
}

extern "C" void kernel_launch(void* const* d_in, const int* in_sizes, int n_in,
                              void* d_out, int out_size)
{
    const float* X  = (const float*)d_in[0];   // (32, 1024, 1024) fp32
    const float* Wt = (const float*)d_in[1];   // (3, 3) fp32
    float* Y        = (float*)d_out;           // (32, 1024, 1024) fp32

    static bool attr_set = false;
    if (!attr_set) {
        cudaFuncSetAttribute(conv3x3_kernel,
                             cudaFuncAttributeMaxDynamicSharedMemorySize,
                             SMEM_BYTES);
        attr_set = true;
    }
    conv3x3_kernel<<<N_CTAS, 256, SMEM_BYTES>>>(X, Wt, Y);
}

// round 14
// speedup vs baseline: 1.1205x; 1.1205x over previous
#include <cuda_runtime.h>
#include <cstdint>

// 3x3 conv, stride 1, pad 1, single channel, X: (32, 1024, 1024) fp32.
// R12 with max occupancy: each CTA computes a 4-row x 1024-col band; the 6
// input rows (24KB contiguous) arrive via ONE cp.async.bulk into static
// smem (mbarrier). __launch_bounds__(256,8) forces <=32 regs -> 8 CTAs/SM
// (~90% occ, 8 outstanding bulk copies per SM feeding the DRAM queue).
// Compute: one-touch rolling 3-row register window; __stcs float4 stores.
// Grid 8192 one-shot CTAs (tail of replay N overlaps head of replay N+1).

#define IMG_W 1024
#define IMG_H 1024
#define ROWS_CTA 4
#define SM_ROWS (ROWS_CTA + 2)

__device__ __forceinline__ uint32_t smem_u32(const void* p) {
    uint32_t a;
    asm("{ .reg .u64 t; cvta.to.shared.u64 t, %1; cvt.u32.u64 %0, t; }"
        : "=r"(a) : "l"(p));
    return a;
}

__global__ __launch_bounds__(256, 8) void conv3x3_kernel(
    const float* __restrict__ X,
    const float* __restrict__ Wt,
    float* __restrict__ Y)
{
    __shared__ __align__(128) float sm[SM_ROWS * IMG_W];
    __shared__ __align__(8)  unsigned long long mbar;

    const int tid   = threadIdx.x;
    const int bx    = blockIdx.x;
    const int batch = bx >> 8;            // / 256 bands
    const int band  = bx & 255;
    const int r0    = band << 2;          // first output row
    const int c0    = tid << 2;           // 4 cols per thread (covers 1024)

    const size_t plane = (size_t)IMG_W * IMG_H;
    const float* Xb = X + (size_t)batch * plane;
    float*       Yb = Y + (size_t)batch * plane;

    const uint32_t mbar_a = smem_u32(&mbar);
    const uint32_t sm_a   = smem_u32(sm);

    if (tid == 0) {
        asm volatile("mbarrier.init.shared.b64 [%0], 1;" :: "r"(mbar_a) : "memory");
    }
    __syncthreads();

    // One contiguous bulk copy: gmem rows [gstart, gend] -> smem rows
    // starting at (gstart - (r0-1)).
    const int r_first = r0 - 1;
    const int gstart  = r_first < 0 ? 0 : r_first;
    const int gend_i  = r0 + ROWS_CTA;                 // halo row below
    const int gend    = gend_i > (IMG_H - 1) ? (IMG_H - 1) : gend_i;
    const uint32_t nbytes = (uint32_t)(gend - gstart + 1) * IMG_W * 4u;
    const uint32_t dst    = sm_a + (uint32_t)(gstart - r_first) * IMG_W * 4u;
    const float*   src    = Xb + (size_t)gstart * IMG_W;

    if (tid == 0) {
        asm volatile("mbarrier.arrive.expect_tx.shared.b64 _, [%0], %1;"
                     :: "r"(mbar_a), "r"(nbytes) : "memory");
        asm volatile(
            "cp.async.bulk.shared::cta.global.mbarrier::complete_tx::bytes "
            "[%0], [%1], %2, [%3];"
            :: "r"(dst), "l"(src), "r"(nbytes), "r"(mbar_a) : "memory");
    }

    // Zero pad rows (never written by the copy) while the copy is in flight.
    if (r_first < 0) {
        float4 z = make_float4(0.f, 0.f, 0.f, 0.f);
        *reinterpret_cast<float4*>(&sm[c0]) = z;
    }
    if (gend_i > IMG_H - 1) {
        float4 z = make_float4(0.f, 0.f, 0.f, 0.f);
        *reinterpret_cast<float4*>(&sm[(SM_ROWS - 1) * IMG_W + c0]) = z;
    }

    // Weights (L2-cached broadcast) while the copy is in flight.
    float w[9];
#pragma unroll
    for (int i = 0; i < 9; i++) w[i] = __ldg(Wt + i);

    // Wait for the bulk copy (phase 0), then sync so pad zeros are visible.
    asm volatile(
        "{\n\t"
        ".reg .pred P;\n\t"
        "WAIT_%=:\n\t"
        "mbarrier.try_wait.parity.acquire.cta.shared::cta.b64 P, [%0], 0;\n\t"
        "@!P bra WAIT_%=;\n\t"
        "}"
        :: "r"(mbar_a) : "memory");
    __syncthreads();

    // Rolling 3-row register window; smem row k = input row r0 + k - 1.
    // Each smem row is read exactly once per thread.
    float b[3][6];

#define LOAD_SMROW(dstbuf, k)                                                 \
    do {                                                                      \
        const float* rp = &sm[(k) * IMG_W];                                   \
        const float4 v = *reinterpret_cast<const float4*>(rp + c0);           \
        (dstbuf)[1] = v.x; (dstbuf)[2] = v.y;                                 \
        (dstbuf)[3] = v.z; (dstbuf)[4] = v.w;                                 \
        (dstbuf)[0] = (c0 > 0)           ? rp[c0 - 1] : 0.0f;                 \
        (dstbuf)[5] = (c0 + 4 < IMG_W)   ? rp[c0 + 4] : 0.0f;                 \
    } while (0)

    LOAD_SMROW(b[0], 0);
    LOAD_SMROW(b[1], 1);

#pragma unroll
    for (int i = 0; i < ROWS_CTA; i++) {
        LOAD_SMROW(b[(i + 2) % 3], i + 2);

        const float* t0 = b[i % 3];         // input row r0+i-1  (ky=0)
        const float* t1 = b[(i + 1) % 3];   // input row r0+i    (ky=1)
        const float* t2 = b[(i + 2) % 3];   // input row r0+i+1  (ky=2)

        float4 o;
        float acc[4];
#pragma unroll
        for (int j = 0; j < 4; j++) {
            float a;
            a = fmaf(w[0], t0[j], fmaf(w[1], t0[j + 1], w[2] * t0[j + 2]));
            a = fmaf(w[3], t1[j], fmaf(w[4], t1[j + 1], fmaf(w[5], t1[j + 2], a)));
            a = fmaf(w[6], t2[j], fmaf(w[7], t2[j + 1], fmaf(w[8], t2[j + 2], a)));
            acc[j] = a;
        }
        o.x = acc[0]; o.y = acc[1]; o.z = acc[2]; o.w = acc[3];
        __stcs(reinterpret_cast<float4*>(Yb + (size_t)(r0 + i) * IMG_W + c0), o);
    }
#undef LOAD_SMROW
}

extern "C" void kernel_launch(void* const* d_in, const int* in_sizes, int n_in,
                              void* d_out, int out_size)
{
    const float* X  = (const float*)d_in[0];   // (32, 1024, 1024) fp32
    const float* Wt = (const float*)d_in[1];   // (3, 3) fp32
    float* Y        = (float*)d_out;           // (32, 1024, 1024) fp32

    const int grid = 32 * 256;                 // batches * 4-row bands
    conv3x3_kernel<<<grid, 256>>>(X, Wt, Y);
}